// round 15
// baseline (speedup 1.0000x reference)
#include <cuda_runtime.h>
#include <cuda_bf16.h>
#include <cuda_fp16.h>
#include <cstdint>

#define NN 50000
#define EE 800000
#define HH 3
#define HIDN 128
#define HF (HH*HIDN)   // 384
#define NCLS 6
#define MBLKS 391      // ceil(50000/128)
#define CAP 128        // per-node cached-edge capacity in fused agg kernel
#define FRAGW (MBLKS*16384)

// weight-fragment scratch offsets (words); bf16 hi/lo packed 2-per-word
#define WF_W1  0
#define WF_W2  49152
#define WF_L1  98304
#define WF_L2  114688
#define WF_L3  131072
#define WF_L4  147456
#define WF_TOT 163840

#define NA_ELEMS (MBLKS*128*64)     // presplit_a items (word pairs)
#define NW_ELEMS 81920              // presplit_w items

// ---------------- scratch (device globals; no allocation allowed) --------
__device__ __half   g_h[NN*HF];     // post-GEMM per-head features (fp16)
__device__ float    g_el[NN*HH];
__device__ float    g_er[NN*HH];
__device__ int      g_srcs[EE];     // src node id in CSR order
__device__ int      g_deg[NN];
__device__ int      g_rowptr[NN+1];
__device__ int      g_wptr[NN];
__device__ uint32_t g_wf[WF_TOT];   // pre-split bf16 weight frags
__device__ uint32_t g_afragA[FRAGW];

// ---------------- helpers -------------------------------------------------
__device__ __forceinline__ uint32_t bfpack2(float e0, float e1, uint32_t& loW) {
    __nv_bfloat16 h0 = __float2bfloat16_rn(e0);
    __nv_bfloat16 h1 = __float2bfloat16_rn(e1);
    float r0 = e0 - __bfloat162float(h0);
    float r1 = e1 - __bfloat162float(h1);
    __nv_bfloat16 l0 = __float2bfloat16_rn(r0);
    __nv_bfloat16 l1 = __float2bfloat16_rn(r1);
    loW = (uint32_t)__bfloat16_as_ushort(l0) | ((uint32_t)__bfloat16_as_ushort(l1) << 16);
    return (uint32_t)__bfloat16_as_ushort(h0) | ((uint32_t)__bfloat16_as_ushort(h1) << 16);
}
__device__ __forceinline__ void mma16(float* c, const uint32_t* a, uint32_t b0, uint32_t b1) {
    asm("mma.sync.aligned.m16n8k16.row.col.f32.bf16.bf16.f32 "
        "{%0,%1,%2,%3}, {%4,%5,%6,%7}, {%8,%9}, {%0,%1,%2,%3};"
        : "+f"(c[0]), "+f"(c[1]), "+f"(c[2]), "+f"(c[3])
        : "r"(a[0]), "r"(a[1]), "r"(a[2]), "r"(a[3]), "r"(b0), "r"(b1));
}
// A-fragment word address (hi plane; lo at +128) for element (row, k even)
__device__ __forceinline__ int frag_addr(int row, int k) {
    int mblk = row >> 7, ch = k >> 4, mtile = (row >> 4) & 7;
    int r16 = row & 15, k16 = k & 15;
    int reg  = (k16 >> 3)*2 + (r16 >> 3);
    int lane = (r16 & 7)*4 + ((k16 >> 1) & 3);
    return ((mblk*8 + ch)*8 + mtile)*256 + lane*4 + reg;
}
__device__ __forceinline__ uint4 ldg4(const uint32_t* p) {
    return *reinterpret_cast<const uint4*>(p);
}
// 12-mma bf16x3 step for one (nA,nB) B pair
__device__ __forceinline__ void mma_step(float acc[2][8][4], const uint4 ah[2],
                                         const uint4 alo[2], uint4 b0, uint4 b1,
                                         int nA, int nB)
{
    mma16(acc[0][nA], (const uint32_t*)&ah[0],  b0.x, b0.y);
    mma16(acc[1][nA], (const uint32_t*)&ah[1],  b0.x, b0.y);
    mma16(acc[0][nB], (const uint32_t*)&ah[0],  b1.x, b1.y);
    mma16(acc[1][nB], (const uint32_t*)&ah[1],  b1.x, b1.y);
    mma16(acc[0][nA], (const uint32_t*)&ah[0],  b0.z, b0.w);
    mma16(acc[1][nA], (const uint32_t*)&ah[1],  b0.z, b0.w);
    mma16(acc[0][nB], (const uint32_t*)&ah[0],  b1.z, b1.w);
    mma16(acc[1][nB], (const uint32_t*)&ah[1],  b1.z, b1.w);
    mma16(acc[0][nA], (const uint32_t*)&alo[0], b0.x, b0.y);
    mma16(acc[1][nA], (const uint32_t*)&alo[1], b0.x, b0.y);
    mma16(acc[0][nB], (const uint32_t*)&alo[0], b1.x, b1.y);
    mma16(acc[1][nB], (const uint32_t*)&alo[1], b1.x, b1.y);
}

// ------- combined pre-split: A frags + all weight frags, one launch ------
__global__ void presplit_kernel(const float* __restrict__ X,
                                const float* __restrict__ W1, const float* __restrict__ W2,
                                const float* __restrict__ L1, const float* __restrict__ L2,
                                const float* __restrict__ L3, const float* __restrict__ L4)
{
    int i = blockIdx.x*blockDim.x + threadIdx.x;
    if (i < NA_ELEMS) {
        int row = i >> 6, k = (i & 63)*2;
        float e0 = 0.f, e1 = 0.f;
        if (row < NN) {
            e0 = X[row*128 + k];
            e1 = X[row*128 + k + 1];
        }
        uint32_t loW;
        uint32_t hiW = bfpack2(e0, e1, loW);
        int a = frag_addr(row, k);
        g_afragA[a]       = hiW;
        g_afragA[a + 128] = loW;
        return;
    }
    int j = i - NA_ELEMS;
    if (j >= NW_ELEMS) return;
    const float* W; int ncols, ooff, rem;
    if      (j < 24576) { W = W1; ncols = 384; ooff = WF_W1; rem = j; }
    else if (j < 49152) { W = W2; ncols = 384; ooff = WF_W2; rem = j - 24576; }
    else if (j < 57344) { W = L1; ncols = 128; ooff = WF_L1; rem = j - 49152; }
    else if (j < 65536) { W = L2; ncols = 128; ooff = WF_L2; rem = j - 57344; }
    else if (j < 73728) { W = L3; ncols = 128; ooff = WF_L3; rem = j - 65536; }
    else                { W = L4; ncols = 128; ooff = WF_L4; rem = j - 73728; }
    int g = rem >> 6, idx = rem & 63;
    int lane = idx >> 1, reg = idx & 1;
    int nt = g & 7, wn = (g >> 3) & 1, ch = (g >> 4) & 7, cb = g >> 7;
    int k = ch*16 + reg*8 + (lane & 3)*2;
    int n = cb*128 + wn*64 + nt*8 + (lane >> 2);
    float e0 = W[k*ncols + n];
    float e1 = W[(k+1)*ncols + n];
    uint32_t loW;
    uint32_t hiW = bfpack2(e0, e1, loW);
    g_wf[ooff + g*128 + lane*4 + reg]     = hiW;
    g_wf[ooff + g*128 + lane*4 + 2 + reg] = loW;
}

// ---------------- CSR build ----------------------------------------------
__global__ void zero_deg_kernel() {
    int i = blockIdx.x*blockDim.x + threadIdx.x;
    if (i < NN) g_deg[i] = 0;
}

__global__ void hist_kernel(const int* __restrict__ dst) {
    int i = blockIdx.x*blockDim.x + threadIdx.x;
    if (i < EE) atomicAdd(&g_deg[dst[i]], 1);
}

__global__ void scan_kernel() {
    __shared__ int sh[1024];
    int t = threadIdx.x;
    const int ITEMS = (NN + 1023) / 1024;
    int base = t * ITEMS;
    int s = 0;
    for (int i = 0; i < ITEMS; i++) {
        int idx = base + i;
        if (idx < NN) s += g_deg[idx];
    }
    sh[t] = s;
    __syncthreads();
    for (int off = 1; off < 1024; off <<= 1) {
        int v = (t >= off) ? sh[t - off] : 0;
        __syncthreads();
        sh[t] += v;
        __syncthreads();
    }
    int run = sh[t] - s;
    for (int i = 0; i < ITEMS; i++) {
        int idx = base + i;
        if (idx < NN) {
            g_rowptr[idx] = run;
            g_wptr[idx]   = run;
            run += g_deg[idx];
        }
    }
    if (t == 0) g_rowptr[NN] = EE;
}

__global__ void scatter_kernel(const int* __restrict__ src, const int* __restrict__ dst) {
    int i = blockIdx.x*blockDim.x + threadIdx.x;
    if (i < EE) {
        int d = dst[i];
        int p = atomicAdd(&g_wptr[d], 1);
        g_srcs[p] = src[i];
    }
}

// ------------- GAT GEMM: bf16x3, smem-free, B software pipeline ----------
// C -> g_h fp16 + attention dots for head hh=blockIdx.x -> g_el/g_er.
__global__ __launch_bounds__(256, 2)
void gatgemm_kernel(const uint32_t* __restrict__ af, const uint32_t* __restrict__ wfp,
                    int M, const float* __restrict__ al, const float* __restrict__ ar)
{
    __shared__ float sEl[2][128], sEr[2][128];
    int tid  = threadIdx.x;
    int lane = tid & 31, warp = tid >> 5;
    int wm = warp >> 1, wn = warp & 1;
    int mblk = blockIdx.y;
    int m0 = mblk*128, col0 = blockIdx.x*128;

    float acc[2][8][4];
    #pragma unroll
    for (int i = 0; i < 2; i++)
        #pragma unroll
        for (int j = 0; j < 8; j++)
            #pragma unroll
            for (int q = 0; q < 4; q++) acc[i][j][q] = 0.f;

    const uint32_t* afb = af  + mblk*16384;
    const uint32_t* wfw = wfp + blockIdx.x*16384 + wn*8*128 + lane*4;

    // B pipeline: (b0,b1) for pair (ch=0, ng=0) preloaded
    uint4 b0 = ldg4(wfw);
    uint4 b1 = ldg4(wfw + 128);

    #pragma unroll 1
    for (int ch = 0; ch < 8; ch++) {
        uint4 ah[2], alo[2];
        #pragma unroll
        for (int mt = 0; mt < 2; mt++) {
            int base = (ch*8 + wm*2 + mt)*256 + lane*4;
            ah[mt]  = ldg4(&afb[base]);
            alo[mt] = ldg4(&afb[base + 128]);
        }
        #pragma unroll
        for (int ng = 0; ng < 4; ng++) {
            uint4 nb0, nb1;
            if (ng < 3) {
                nb0 = ldg4(wfw + (ch*16 + 2*ng + 2)*128);
                nb1 = ldg4(wfw + (ch*16 + 2*ng + 3)*128);
            } else if (ch < 7) {
                nb0 = ldg4(wfw + ((ch+1)*16)*128);
                nb1 = ldg4(wfw + ((ch+1)*16 + 1)*128);
            }
            mma_step(acc, ah, alo, b0, b1, 2*ng, 2*ng + 1);
            b0 = nb0; b1 = nb1;
        }
    }

    // ---- fp16 h store ----
    #pragma unroll
    for (int mt = 0; mt < 2; mt++) {
        #pragma unroll
        for (int half = 0; half < 2; half++) {
            int r = m0 + wm*32 + mt*16 + (lane >> 2) + half*8;
            if (r >= M) continue;
            #pragma unroll
            for (int nt = 0; nt < 8; nt++) {
                int c = col0 + wn*64 + nt*8 + 2*(lane & 3);
                __half2 hv = __float22half2_rn(
                    make_float2(acc[mt][nt][half*2 + 0], acc[mt][nt][half*2 + 1]));
                *reinterpret_cast<__half2*>(&g_h[(size_t)r*HF + c]) = hv;
            }
        }
    }
    // ---- fused attention dots ----
    int hh = blockIdx.x;
    float alv[8][2], arv[8][2];
    #pragma unroll
    for (int nt = 0; nt < 8; nt++)
        #pragma unroll
        for (int j = 0; j < 2; j++) {
            int c = wn*64 + nt*8 + 2*(lane & 3) + j;
            alv[nt][j] = __ldg(&al[hh*HIDN + c]);
            arv[nt][j] = __ldg(&ar[hh*HIDN + c]);
        }
    #pragma unroll
    for (int mt = 0; mt < 2; mt++) {
        #pragma unroll
        for (int half = 0; half < 2; half++) {
            float pl = 0.f, pr = 0.f;
            #pragma unroll
            for (int nt = 0; nt < 8; nt++)
                #pragma unroll
                for (int j = 0; j < 2; j++) {
                    float v = acc[mt][nt][half*2 + j];
                    pl += v * alv[nt][j];
                    pr += v * arv[nt][j];
                }
            pl += __shfl_xor_sync(0xffffffffu, pl, 1);
            pl += __shfl_xor_sync(0xffffffffu, pl, 2);
            pr += __shfl_xor_sync(0xffffffffu, pr, 1);
            pr += __shfl_xor_sync(0xffffffffu, pr, 2);
            if ((lane & 3) == 0) {
                int rl = wm*32 + mt*16 + (lane >> 2) + half*8;
                sEl[wn][rl] = pl;
                sEr[wn][rl] = pr;
            }
        }
    }
    __syncthreads();
    if (tid < 128) {
        int r = m0 + tid;
        if (r < M) {
            g_el[r*HH + hh] = sEl[0][tid] + sEl[1][tid];
            g_er[r*HH + hh] = sEr[0][tid] + sEr[1][tid];
        }
    }
}

// ------------- fused MLP: lin1..lin4 + classifier in one kernel ----------
__global__ __launch_bounds__(256, 2)
void mlp_kernel(const uint32_t* __restrict__ af, const uint32_t* __restrict__ wfbase,
                const float* __restrict__ lb1, const float* __restrict__ lb2,
                const float* __restrict__ lb3, const float* __restrict__ lb4,
                const float* __restrict__ lw5, const float* __restrict__ lb5,
                float* __restrict__ out, int M)
{
    extern __shared__ uint32_t sF[];   // 16384 words = 64 KB
    int tid  = threadIdx.x;
    int lane = tid & 31, warp = tid >> 5;
    int wm = warp >> 1, wn = warp & 1;
    int mblk = blockIdx.x;
    int m0 = mblk*128;

    const float* midbias[3] = {lb1, lb2, lb3};
    const int woff[4] = {WF_L1, WF_L2, WF_L3, WF_L4};

    float acc[2][8][4];
    #pragma unroll
    for (int i = 0; i < 2; i++)
        #pragma unroll
        for (int j = 0; j < 8; j++)
            #pragma unroll
            for (int q = 0; q < 4; q++) acc[i][j][q] = 0.f;

    // ---- layer 1: A from global frags ----
    {
        const uint32_t* afb = af + mblk*16384;
        const uint32_t* wfw = wfbase + woff[0] + wn*8*128 + lane*4;
        uint4 b0 = ldg4(wfw);
        uint4 b1 = ldg4(wfw + 128);
        #pragma unroll 1
        for (int ch = 0; ch < 8; ch++) {
            uint4 ah[2], alo[2];
            #pragma unroll
            for (int mt = 0; mt < 2; mt++) {
                int base = (ch*8 + wm*2 + mt)*256 + lane*4;
                ah[mt]  = ldg4(&afb[base]);
                alo[mt] = ldg4(&afb[base + 128]);
            }
            #pragma unroll
            for (int ng = 0; ng < 4; ng++) {
                uint4 nb0, nb1;
                if (ng < 3) {
                    nb0 = ldg4(wfw + (ch*16 + 2*ng + 2)*128);
                    nb1 = ldg4(wfw + (ch*16 + 2*ng + 3)*128);
                } else if (ch < 7) {
                    nb0 = ldg4(wfw + ((ch+1)*16)*128);
                    nb1 = ldg4(wfw + ((ch+1)*16 + 1)*128);
                }
                mma_step(acc, ah, alo, b0, b1, 2*ng, 2*ng + 1);
                b0 = nb0; b1 = nb1;
            }
        }
    }

    // ---- layers 2..4: frag exchange via smem ----
    #pragma unroll 1
    for (int l = 1; l < 4; l++) {
        const float* bias = midbias[l-1];
        #pragma unroll
        for (int mt = 0; mt < 2; mt++) {
            #pragma unroll
            for (int ng = 0; ng < 4; ng++) {
                int ntE = 2*ng, ntO = 2*ng + 1;
                int cE = wn*64 + ntE*8 + 2*(lane & 3);
                float bE0 = bias[cE],     bE1 = bias[cE + 1];
                float bO0 = bias[cE + 8], bO1 = bias[cE + 9];
                float e0 = acc[mt][ntE][0] + bE0, e1 = acc[mt][ntE][1] + bE1;
                float e2 = acc[mt][ntE][2] + bE0, e3 = acc[mt][ntE][3] + bE1;
                float o0 = acc[mt][ntO][0] + bO0, o1 = acc[mt][ntO][1] + bO1;
                float o2 = acc[mt][ntO][2] + bO0, o3 = acc[mt][ntO][3] + bO1;
                e0 = e0 > 0.f ? e0 : 0.01f*e0;  e1 = e1 > 0.f ? e1 : 0.01f*e1;
                e2 = e2 > 0.f ? e2 : 0.01f*e2;  e3 = e3 > 0.f ? e3 : 0.01f*e3;
                o0 = o0 > 0.f ? o0 : 0.01f*o0;  o1 = o1 > 0.f ? o1 : 0.01f*o1;
                o2 = o2 > 0.f ? o2 : 0.01f*o2;  o3 = o3 > 0.f ? o3 : 0.01f*o3;
                uint32_t l0, l1, l2, l3;
                uint32_t h0 = bfpack2(e0, e1, l0);
                uint32_t h1 = bfpack2(e2, e3, l1);
                uint32_t h2 = bfpack2(o0, o1, l2);
                uint32_t h3 = bfpack2(o2, o3, l3);
                int base = ((wn*4 + ng)*8 + wm*2 + mt)*256 + lane*4;
                *reinterpret_cast<uint4*>(&sF[base])       = make_uint4(h0, h1, h2, h3);
                *reinterpret_cast<uint4*>(&sF[base + 128]) = make_uint4(l0, l1, l2, l3);
                #pragma unroll
                for (int q = 0; q < 4; q++) { acc[mt][ntE][q] = 0.f; acc[mt][ntO][q] = 0.f; }
            }
        }
        __syncthreads();
        const uint32_t* wfw = wfbase + woff[l] + wn*8*128 + lane*4;
        uint4 b0 = ldg4(wfw);
        uint4 b1 = ldg4(wfw + 128);
        #pragma unroll 1
        for (int ch = 0; ch < 8; ch++) {
            uint4 ah[2], alo[2];
            #pragma unroll
            for (int mt = 0; mt < 2; mt++) {
                int base = (ch*8 + wm*2 + mt)*256 + lane*4;
                ah[mt]  = *reinterpret_cast<const uint4*>(&sF[base]);
                alo[mt] = *reinterpret_cast<const uint4*>(&sF[base + 128]);
            }
            #pragma unroll
            for (int ng = 0; ng < 4; ng++) {
                uint4 nb0, nb1;
                if (ng < 3) {
                    nb0 = ldg4(wfw + (ch*16 + 2*ng + 2)*128);
                    nb1 = ldg4(wfw + (ch*16 + 2*ng + 3)*128);
                } else if (ch < 7) {
                    nb0 = ldg4(wfw + ((ch+1)*16)*128);
                    nb1 = ldg4(wfw + ((ch+1)*16 + 1)*128);
                }
                mma_step(acc, ah, alo, b0, b1, 2*ng, 2*ng + 1);
                b0 = nb0; b1 = nb1;
            }
        }
        __syncthreads();   // reads done before next conversion overwrites
    }

    // ---- final: lb4 + leaky, then fused classifier (x @ lw5 + lb5) ------
    float* sC = reinterpret_cast<float*>(sF);   // [ (wn*128 + rl)*8 + cls ]
    #pragma unroll
    for (int mt = 0; mt < 2; mt++) {
        #pragma unroll
        for (int half = 0; half < 2; half++) {
            float part[NCLS] = {0.f, 0.f, 0.f, 0.f, 0.f, 0.f};
            #pragma unroll
            for (int nt = 0; nt < 8; nt++) {
                #pragma unroll
                for (int j = 0; j < 2; j++) {
                    int c = wn*64 + nt*8 + 2*(lane & 3) + j;
                    float v = acc[mt][nt][half*2 + j] + lb4[c];
                    v = v > 0.f ? v : 0.01f*v;
                    #pragma unroll
                    for (int cls = 0; cls < NCLS; cls++)
                        part[cls] += v * __ldg(&lw5[c*NCLS + cls]);
                }
            }
            #pragma unroll
            for (int cls = 0; cls < NCLS; cls++) {
                part[cls] += __shfl_xor_sync(0xffffffffu, part[cls], 1);
                part[cls] += __shfl_xor_sync(0xffffffffu, part[cls], 2);
            }
            if ((lane & 3) == 0) {
                int rl = wm*32 + mt*16 + (lane >> 2) + half*8;
                #pragma unroll
                for (int cls = 0; cls < NCLS; cls++)
                    sC[(wn*128 + rl)*8 + cls] = part[cls];
            }
        }
    }
    __syncthreads();
    for (int idx = tid; idx < 128*NCLS; idx += 256) {
        int rl = idx / NCLS, cls = idx % NCLS;
        int r = m0 + rl;
        if (r < M)
            out[(size_t)r*NCLS + cls] =
                sC[rl*8 + cls] + sC[(128 + rl)*8 + cls] + lb5[cls];
    }
}

// ---- fused softmax + aggregation, block (96 thr) per node ---------------
__global__ __launch_bounds__(96)
void agg_kernel(const float* __restrict__ bias, uint32_t* __restrict__ fragOut)
{
    __shared__ int    sSrc[CAP];
    __shared__ float  sE[3][CAP];
    __shared__ float4 sh4[3][32];
    int n = blockIdx.x;
    int t = threadIdx.x, head = t >> 5, lane = t & 31;
    int beg = g_rowptr[n], end = g_rowptr[n+1];
    int deg = end - beg;
    int cached = deg < CAP ? deg : CAP;
    for (int j = t; j < cached; j += 96) sSrc[j] = g_srcs[beg + j];
    __syncthreads();

    float er_n = g_er[n*HH + head];
    float mx = -1e30f;
    for (int j = lane; j < deg; j += 32) {
        int s = (j < CAP) ? sSrc[j] : g_srcs[beg + j];
        float v = g_el[s*HH + head] + er_n;
        v = v > 0.f ? v : 0.2f*v;
        if (j < CAP) sE[head][j] = v;
        mx = fmaxf(mx, v);
    }
    #pragma unroll
    for (int o = 16; o; o >>= 1) mx = fmaxf(mx, __shfl_xor_sync(0xffffffffu, mx, o));
    float sum = 0.f;
    for (int j = lane; j < deg; j += 32) {
        float v;
        if (j < CAP) v = sE[head][j];
        else {
            int s = g_srcs[beg + j];
            v = g_el[s*HH + head] + er_n;
            v = v > 0.f ? v : 0.2f*v;
        }
        float e = expf(v - mx);
        if (j < CAP) sE[head][j] = e;
        sum += e;
    }
    #pragma unroll
    for (int o = 16; o; o >>= 1) sum += __shfl_xor_sync(0xffffffffu, sum, o);
    float inv = 1.f / (sum + 1e-9f);
    __syncwarp();

    // weighted gather, unroll 4 (MLP_eff ~4)
    const __half* hb = &g_h[head*HIDN + lane*4];
    float4 a = make_float4(0.f, 0.f, 0.f, 0.f);
    int jn = 0;
    for (; jn + 3 < cached; jn += 4) {
        int   s0 = sSrc[jn],   s1 = sSrc[jn+1], s2 = sSrc[jn+2], s3 = sSrc[jn+3];
        float w0 = sE[head][jn],   w1 = sE[head][jn+1];
        float w2 = sE[head][jn+2], w3 = sE[head][jn+3];
        uint2 u0 = *(const uint2*)&hb[(size_t)s0*HF];
        uint2 u1 = *(const uint2*)&hb[(size_t)s1*HF];
        uint2 u2 = *(const uint2*)&hb[(size_t)s2*HF];
        uint2 u3 = *(const uint2*)&hb[(size_t)s3*HF];
        float2 p00 = __half22float2(*reinterpret_cast<__half2*>(&u0.x));
        float2 p01 = __half22float2(*reinterpret_cast<__half2*>(&u0.y));
        float2 p10 = __half22float2(*reinterpret_cast<__half2*>(&u1.x));
        float2 p11 = __half22float2(*reinterpret_cast<__half2*>(&u1.y));
        float2 p20 = __half22float2(*reinterpret_cast<__half2*>(&u2.x));
        float2 p21 = __half22float2(*reinterpret_cast<__half2*>(&u2.y));
        float2 p30 = __half22float2(*reinterpret_cast<__half2*>(&u3.x));
        float2 p31 = __half22float2(*reinterpret_cast<__half2*>(&u3.y));
        a.x += w0*p00.x + w1*p10.x + w2*p20.x + w3*p30.x;
        a.y += w0*p00.y + w1*p10.y + w2*p20.y + w3*p30.y;
        a.z += w0*p01.x + w1*p11.x + w2*p21.x + w3*p31.x;
        a.w += w0*p01.y + w1*p11.y + w2*p21.y + w3*p31.y;
    }
    for (; jn < cached; jn++) {
        int s = sSrc[jn];
        float w = sE[head][jn];
        uint2 u = *(const uint2*)&hb[(size_t)s*HF];
        float2 p0 = __half22float2(*reinterpret_cast<__half2*>(&u.x));
        float2 p1 = __half22float2(*reinterpret_cast<__half2*>(&u.y));
        a.x += w*p0.x; a.y += w*p0.y; a.z += w*p1.x; a.w += w*p1.y;
    }
    for (int j = beg + CAP; j < end; j++) {      // rare fallback
        int s = g_srcs[j];
        float v = g_el[s*HH + head] + er_n;
        v = v > 0.f ? v : 0.2f*v;
        float w = expf(v - mx);
        uint2 u = *(const uint2*)&hb[(size_t)s*HF];
        float2 p0 = __half22float2(*reinterpret_cast<__half2*>(&u.x));
        float2 p1 = __half22float2(*reinterpret_cast<__half2*>(&u.y));
        a.x += w*p0.x; a.y += w*p0.y; a.z += w*p1.x; a.w += w*p1.y;
    }

    const float4 b4 = *(const float4*)&bias[head*HIDN + lane*4];
    a.x = a.x*inv + b4.x;  a.y = a.y*inv + b4.y;
    a.z = a.z*inv + b4.z;  a.w = a.w*inv + b4.w;
    a.x = a.x > 0.f ? a.x : 0.01f*a.x;
    a.y = a.y > 0.f ? a.y : 0.01f*a.y;
    a.z = a.z > 0.f ? a.z : 0.01f*a.z;
    a.w = a.w > 0.f ? a.w : 0.01f*a.w;
    sh4[head][lane] = a;
    __syncthreads();
    if (t < 32) {
        float4 r0 = sh4[0][t], r1 = sh4[1][t], r2 = sh4[2][t];
        float o[4];
        o[0] = (r0.x + r1.x + r2.x) * (1.f/3.f);
        o[1] = (r0.y + r1.y + r2.y) * (1.f/3.f);
        o[2] = (r0.z + r1.z + r2.z) * (1.f/3.f);
        o[3] = (r0.w + r1.w + r2.w) * (1.f/3.f);
        uint32_t lo01, lo23;
        uint32_t hi01 = bfpack2(o[0], o[1], lo01);
        uint32_t hi23 = bfpack2(o[2], o[3], lo23);
        int a0 = frag_addr(n, t*4);
        int a2 = frag_addr(n, t*4 + 2);
        fragOut[a0]       = hi01;
        fragOut[a0 + 128] = lo01;
        fragOut[a2]       = hi23;
        fragOut[a2 + 128] = lo23;
    }
}

// -------------------------------------------------------------------------
extern "C" void kernel_launch(void* const* d_in, const int* in_sizes, int n_in,
                              void* d_out, int out_size)
{
    const float* in_feat = (const float*)d_in[0];
    const int*   src     = (const int*)  d_in[1];
    const int*   dst     = (const int*)  d_in[2];
    const float* W1  = (const float*)d_in[3];
    const float* al1 = (const float*)d_in[4];
    const float* ar1 = (const float*)d_in[5];
    const float* b1  = (const float*)d_in[6];
    const float* W2  = (const float*)d_in[7];
    const float* al2 = (const float*)d_in[8];
    const float* ar2 = (const float*)d_in[9];
    const float* b2  = (const float*)d_in[10];
    const float* lw1 = (const float*)d_in[11];
    const float* lb1 = (const float*)d_in[12];
    const float* lw2 = (const float*)d_in[13];
    const float* lb2 = (const float*)d_in[14];
    const float* lw3 = (const float*)d_in[15];
    const float* lb3 = (const float*)d_in[16];
    const float* lw4 = (const float*)d_in[17];
    const float* lb4 = (const float*)d_in[18];
    const float* lw5 = (const float*)d_in[19];
    const float* lb5 = (const float*)d_in[20];
    float* out = (float*)d_out;

    uint32_t *pwf, *pfA;
    cudaGetSymbolAddress((void**)&pwf, g_wf);
    cudaGetSymbolAddress((void**)&pfA, g_afragA);

    cudaFuncSetAttribute(mlp_kernel, cudaFuncAttributeMaxDynamicSharedMemorySize, 65536);

    const int TB = 256;
    dim3 g_gat(HF/128, MBLKS);     // (3, 391)

    // Round-13-proven resource footprint: ONE side stream + TWO events,
    // created fresh per call (no caching, no device allocation).
    cudaStream_t s2;
    cudaStreamCreateWithFlags(&s2, cudaStreamNonBlocking);
    cudaEvent_t eFork, eCSR;
    cudaEventCreateWithFlags(&eFork, cudaEventDisableTiming);
    cudaEventCreateWithFlags(&eCSR,  cudaEventDisableTiming);

    // fork
    cudaEventRecord(eFork, 0);
    cudaStreamWaitEvent(s2, eFork, 0);

    // ---- branch B (s2): CSR build ----
    zero_deg_kernel<<<(NN + TB - 1)/TB, TB, 0, s2>>>();
    hist_kernel<<<(EE + TB - 1)/TB, TB, 0, s2>>>(dst);
    scan_kernel<<<1, 1024, 0, s2>>>();
    scatter_kernel<<<(EE + TB - 1)/TB, TB, 0, s2>>>(src, dst);
    cudaEventRecord(eCSR, s2);

    // ---- branch A (main): combined pre-split (A ∥ W), then gemm1 ----
    presplit_kernel<<<(NA_ELEMS + NW_ELEMS + TB - 1)/TB, TB>>>(
        in_feat, W1, W2, lw1, lw2, lw3, lw4);
    gatgemm_kernel<<<g_gat, 256>>>(pfA, pwf + WF_W1, NN, al1, ar1);

    // join CSR before agg1
    cudaStreamWaitEvent(0, eCSR, 0);

    // ---- GAT layer 1 edge phase ----
    agg_kernel<<<NN, 96>>>(b1, pfA);

    // ---- GAT layer 2 ----
    gatgemm_kernel<<<g_gat, 256>>>(pfA, pwf + WF_W2, NN, al2, ar2);
    agg_kernel<<<NN, 96>>>(b2, pfA);

    // ---- fused MLP (lin1..lin4 + classifier) ----
    mlp_kernel<<<MBLKS, 256, 65536>>>(pfA, pwf, lb1, lb2, lb3, lb4, lw5, lb5, out, NN);
}

// round 16
// speedup vs baseline: 1.5593x; 1.5593x over previous
#include <cuda_runtime.h>
#include <cuda_bf16.h>
#include <cuda_fp16.h>
#include <cstdint>

#define NN 50000
#define EE 800000
#define HH 3
#define HIDN 128
#define HF (HH*HIDN)   // 384
#define NCLS 6
#define MBLKS 391      // ceil(50000/128)
#define CAP 128        // per-node cached-edge capacity in fused agg kernel
#define FRAGW (MBLKS*16384)

// weight-fragment scratch offsets (words); bf16 hi/lo packed 2-per-word
#define WF_W1  0
#define WF_W2  49152
#define WF_L1  98304
#define WF_L2  114688
#define WF_L3  131072
#define WF_L4  147456
#define WF_TOT 163840

// ---------------- scratch (device globals; no allocation allowed) --------
__device__ __half   g_h[NN*HF];     // post-GEMM per-head features (fp16)
__device__ float    g_el[NN*HH];
__device__ float    g_er[NN*HH];
__device__ int      g_srcs[EE];     // src node id in CSR order
__device__ int      g_deg[NN];
__device__ int      g_rowptr[NN+1];
__device__ int      g_wptr[NN];
__device__ uint32_t g_wf[WF_TOT];   // pre-split bf16 weight frags
__device__ uint32_t g_afragA[FRAGW];

// ---------------- helpers -------------------------------------------------
__device__ __forceinline__ uint32_t bfpack2(float e0, float e1, uint32_t& loW) {
    __nv_bfloat16 h0 = __float2bfloat16_rn(e0);
    __nv_bfloat16 h1 = __float2bfloat16_rn(e1);
    float r0 = e0 - __bfloat162float(h0);
    float r1 = e1 - __bfloat162float(h1);
    __nv_bfloat16 l0 = __float2bfloat16_rn(r0);
    __nv_bfloat16 l1 = __float2bfloat16_rn(r1);
    loW = (uint32_t)__bfloat16_as_ushort(l0) | ((uint32_t)__bfloat16_as_ushort(l1) << 16);
    return (uint32_t)__bfloat16_as_ushort(h0) | ((uint32_t)__bfloat16_as_ushort(h1) << 16);
}
__device__ __forceinline__ void mma16(float* c, const uint32_t* a, uint32_t b0, uint32_t b1) {
    asm("mma.sync.aligned.m16n8k16.row.col.f32.bf16.bf16.f32 "
        "{%0,%1,%2,%3}, {%4,%5,%6,%7}, {%8,%9}, {%0,%1,%2,%3};"
        : "+f"(c[0]), "+f"(c[1]), "+f"(c[2]), "+f"(c[3])
        : "r"(a[0]), "r"(a[1]), "r"(a[2]), "r"(a[3]), "r"(b0), "r"(b1));
}
// A-fragment word address (hi plane; lo at +128) for element (row, k even)
__device__ __forceinline__ int frag_addr(int row, int k) {
    int mblk = row >> 7, ch = k >> 4, mtile = (row >> 4) & 7;
    int r16 = row & 15, k16 = k & 15;
    int reg  = (k16 >> 3)*2 + (r16 >> 3);
    int lane = (r16 & 7)*4 + ((k16 >> 1) & 3);
    return ((mblk*8 + ch)*8 + mtile)*256 + lane*4 + reg;
}
__device__ __forceinline__ uint4 ldg4(const uint32_t* p) {
    return *reinterpret_cast<const uint4*>(p);
}
// 12-mma bf16x3 step for one (nA,nB) B pair
__device__ __forceinline__ void mma_step(float acc[2][8][4], const uint4 ah[2],
                                         const uint4 alo[2], uint4 b0, uint4 b1,
                                         int nA, int nB)
{
    mma16(acc[0][nA], (const uint32_t*)&ah[0],  b0.x, b0.y);
    mma16(acc[1][nA], (const uint32_t*)&ah[1],  b0.x, b0.y);
    mma16(acc[0][nB], (const uint32_t*)&ah[0],  b1.x, b1.y);
    mma16(acc[1][nB], (const uint32_t*)&ah[1],  b1.x, b1.y);
    mma16(acc[0][nA], (const uint32_t*)&ah[0],  b0.z, b0.w);
    mma16(acc[1][nA], (const uint32_t*)&ah[1],  b0.z, b0.w);
    mma16(acc[0][nB], (const uint32_t*)&ah[0],  b1.z, b1.w);
    mma16(acc[1][nB], (const uint32_t*)&ah[1],  b1.z, b1.w);
    mma16(acc[0][nA], (const uint32_t*)&alo[0], b0.x, b0.y);
    mma16(acc[1][nA], (const uint32_t*)&alo[1], b0.x, b0.y);
    mma16(acc[0][nB], (const uint32_t*)&alo[0], b1.x, b1.y);
    mma16(acc[1][nB], (const uint32_t*)&alo[1], b1.x, b1.y);
}

// ---------------- pre-split kernels --------------------------------------
__global__ void presplit_w_kernel(const float* __restrict__ W1, const float* __restrict__ W2,
                                  const float* __restrict__ L1, const float* __restrict__ L2,
                                  const float* __restrict__ L3, const float* __restrict__ L4)
{
    int i = blockIdx.x*blockDim.x + threadIdx.x;
    if (i >= 81920) return;
    const float* W; int ncols, ooff, rem;
    if      (i < 24576) { W = W1; ncols = 384; ooff = WF_W1; rem = i; }
    else if (i < 49152) { W = W2; ncols = 384; ooff = WF_W2; rem = i - 24576; }
    else if (i < 57344) { W = L1; ncols = 128; ooff = WF_L1; rem = i - 49152; }
    else if (i < 65536) { W = L2; ncols = 128; ooff = WF_L2; rem = i - 57344; }
    else if (i < 73728) { W = L3; ncols = 128; ooff = WF_L3; rem = i - 65536; }
    else                { W = L4; ncols = 128; ooff = WF_L4; rem = i - 73728; }
    int g = rem >> 6, idx = rem & 63;
    int lane = idx >> 1, reg = idx & 1;
    int nt = g & 7, wn = (g >> 3) & 1, ch = (g >> 4) & 7, cb = g >> 7;
    int k = ch*16 + reg*8 + (lane & 3)*2;
    int n = cb*128 + wn*64 + nt*8 + (lane >> 2);
    float e0 = W[k*ncols + n];
    float e1 = W[(k+1)*ncols + n];
    uint32_t loW;
    uint32_t hiW = bfpack2(e0, e1, loW);
    g_wf[ooff + g*128 + lane*4 + reg]     = hiW;
    g_wf[ooff + g*128 + lane*4 + 2 + reg] = loW;
}

__global__ void presplit_a_kernel(const float* __restrict__ X)
{
    int i = blockIdx.x*blockDim.x + threadIdx.x;
    if (i >= MBLKS*128*64) return;
    int row = i >> 6, k = (i & 63)*2;
    float e0 = 0.f, e1 = 0.f;
    if (row < NN) {
        e0 = X[row*128 + k];
        e1 = X[row*128 + k + 1];
    }
    uint32_t loW;
    uint32_t hiW = bfpack2(e0, e1, loW);
    int a = frag_addr(row, k);
    g_afragA[a]       = hiW;
    g_afragA[a + 128] = loW;
}

// ---------------- CSR build ----------------------------------------------
__global__ void zero_deg_kernel() {
    int i = blockIdx.x*blockDim.x + threadIdx.x;
    if (i < NN) g_deg[i] = 0;
}

__global__ void hist_kernel(const int* __restrict__ dst) {
    int i = blockIdx.x*blockDim.x + threadIdx.x;
    if (i < EE) atomicAdd(&g_deg[dst[i]], 1);
}

__global__ void scan_kernel() {
    __shared__ int sh[1024];
    int t = threadIdx.x;
    const int ITEMS = (NN + 1023) / 1024;
    int base = t * ITEMS;
    int s = 0;
    for (int i = 0; i < ITEMS; i++) {
        int idx = base + i;
        if (idx < NN) s += g_deg[idx];
    }
    sh[t] = s;
    __syncthreads();
    for (int off = 1; off < 1024; off <<= 1) {
        int v = (t >= off) ? sh[t - off] : 0;
        __syncthreads();
        sh[t] += v;
        __syncthreads();
    }
    int run = sh[t] - s;
    for (int i = 0; i < ITEMS; i++) {
        int idx = base + i;
        if (idx < NN) {
            g_rowptr[idx] = run;
            g_wptr[idx]   = run;
            run += g_deg[idx];
        }
    }
    if (t == 0) g_rowptr[NN] = EE;
}

__global__ void scatter_kernel(const int* __restrict__ src, const int* __restrict__ dst) {
    int i = blockIdx.x*blockDim.x + threadIdx.x;
    if (i < EE) {
        int d = dst[i];
        int p = atomicAdd(&g_wptr[d], 1);
        g_srcs[p] = src[i];
    }
}

// ------------- GAT GEMM: bf16x3, smem-free, B software pipeline ----------
// C -> g_h fp16 + attention dots for head hh=blockIdx.x -> g_el/g_er.
__global__ __launch_bounds__(256, 2)
void gatgemm_kernel(const uint32_t* __restrict__ af, const uint32_t* __restrict__ wfp,
                    int M, const float* __restrict__ al, const float* __restrict__ ar)
{
    __shared__ float sEl[2][128], sEr[2][128];
    int tid  = threadIdx.x;
    int lane = tid & 31, warp = tid >> 5;
    int wm = warp >> 1, wn = warp & 1;
    int mblk = blockIdx.y;
    int m0 = mblk*128, col0 = blockIdx.x*128;

    float acc[2][8][4];
    #pragma unroll
    for (int i = 0; i < 2; i++)
        #pragma unroll
        for (int j = 0; j < 8; j++)
            #pragma unroll
            for (int q = 0; q < 4; q++) acc[i][j][q] = 0.f;

    const uint32_t* afb = af  + mblk*16384;
    const uint32_t* wfw = wfp + blockIdx.x*16384 + wn*8*128 + lane*4;

    // B pipeline: (b0,b1) for pair (ch=0, ng=0) preloaded
    uint4 b0 = ldg4(wfw);
    uint4 b1 = ldg4(wfw + 128);

    #pragma unroll 1
    for (int ch = 0; ch < 8; ch++) {
        uint4 ah[2], alo[2];
        #pragma unroll
        for (int mt = 0; mt < 2; mt++) {
            int base = (ch*8 + wm*2 + mt)*256 + lane*4;
            ah[mt]  = ldg4(&afb[base]);
            alo[mt] = ldg4(&afb[base + 128]);
        }
        #pragma unroll
        for (int ng = 0; ng < 4; ng++) {
            uint4 nb0, nb1;
            if (ng < 3) {
                nb0 = ldg4(wfw + (ch*16 + 2*ng + 2)*128);
                nb1 = ldg4(wfw + (ch*16 + 2*ng + 3)*128);
            } else if (ch < 7) {
                nb0 = ldg4(wfw + ((ch+1)*16)*128);
                nb1 = ldg4(wfw + ((ch+1)*16 + 1)*128);
            }
            mma_step(acc, ah, alo, b0, b1, 2*ng, 2*ng + 1);
            b0 = nb0; b1 = nb1;
        }
    }

    // ---- fp16 h store ----
    #pragma unroll
    for (int mt = 0; mt < 2; mt++) {
        #pragma unroll
        for (int half = 0; half < 2; half++) {
            int r = m0 + wm*32 + mt*16 + (lane >> 2) + half*8;
            if (r >= M) continue;
            #pragma unroll
            for (int nt = 0; nt < 8; nt++) {
                int c = col0 + wn*64 + nt*8 + 2*(lane & 3);
                __half2 hv = __float22half2_rn(
                    make_float2(acc[mt][nt][half*2 + 0], acc[mt][nt][half*2 + 1]));
                *reinterpret_cast<__half2*>(&g_h[(size_t)r*HF + c]) = hv;
            }
        }
    }
    // ---- fused attention dots ----
    int hh = blockIdx.x;
    float alv[8][2], arv[8][2];
    #pragma unroll
    for (int nt = 0; nt < 8; nt++)
        #pragma unroll
        for (int j = 0; j < 2; j++) {
            int c = wn*64 + nt*8 + 2*(lane & 3) + j;
            alv[nt][j] = __ldg(&al[hh*HIDN + c]);
            arv[nt][j] = __ldg(&ar[hh*HIDN + c]);
        }
    #pragma unroll
    for (int mt = 0; mt < 2; mt++) {
        #pragma unroll
        for (int half = 0; half < 2; half++) {
            float pl = 0.f, pr = 0.f;
            #pragma unroll
            for (int nt = 0; nt < 8; nt++)
                #pragma unroll
                for (int j = 0; j < 2; j++) {
                    float v = acc[mt][nt][half*2 + j];
                    pl += v * alv[nt][j];
                    pr += v * arv[nt][j];
                }
            pl += __shfl_xor_sync(0xffffffffu, pl, 1);
            pl += __shfl_xor_sync(0xffffffffu, pl, 2);
            pr += __shfl_xor_sync(0xffffffffu, pr, 1);
            pr += __shfl_xor_sync(0xffffffffu, pr, 2);
            if ((lane & 3) == 0) {
                int rl = wm*32 + mt*16 + (lane >> 2) + half*8;
                sEl[wn][rl] = pl;
                sEr[wn][rl] = pr;
            }
        }
    }
    __syncthreads();
    if (tid < 128) {
        int r = m0 + tid;
        if (r < M) {
            g_el[r*HH + hh] = sEl[0][tid] + sEl[1][tid];
            g_er[r*HH + hh] = sEr[0][tid] + sEr[1][tid];
        }
    }
}

// ------------- fused MLP: lin1..lin4 + classifier in one kernel ----------
__global__ __launch_bounds__(256, 2)
void mlp_kernel(const uint32_t* __restrict__ af, const uint32_t* __restrict__ wfbase,
                const float* __restrict__ lb1, const float* __restrict__ lb2,
                const float* __restrict__ lb3, const float* __restrict__ lb4,
                const float* __restrict__ lw5, const float* __restrict__ lb5,
                float* __restrict__ out, int M)
{
    extern __shared__ uint32_t sF[];   // 16384 words = 64 KB
    int tid  = threadIdx.x;
    int lane = tid & 31, warp = tid >> 5;
    int wm = warp >> 1, wn = warp & 1;
    int mblk = blockIdx.x;
    int m0 = mblk*128;

    const float* midbias[3] = {lb1, lb2, lb3};
    const int woff[4] = {WF_L1, WF_L2, WF_L3, WF_L4};

    float acc[2][8][4];
    #pragma unroll
    for (int i = 0; i < 2; i++)
        #pragma unroll
        for (int j = 0; j < 8; j++)
            #pragma unroll
            for (int q = 0; q < 4; q++) acc[i][j][q] = 0.f;

    // ---- layer 1: A from global frags ----
    {
        const uint32_t* afb = af + mblk*16384;
        const uint32_t* wfw = wfbase + woff[0] + wn*8*128 + lane*4;
        uint4 b0 = ldg4(wfw);
        uint4 b1 = ldg4(wfw + 128);
        #pragma unroll 1
        for (int ch = 0; ch < 8; ch++) {
            uint4 ah[2], alo[2];
            #pragma unroll
            for (int mt = 0; mt < 2; mt++) {
                int base = (ch*8 + wm*2 + mt)*256 + lane*4;
                ah[mt]  = ldg4(&afb[base]);
                alo[mt] = ldg4(&afb[base + 128]);
            }
            #pragma unroll
            for (int ng = 0; ng < 4; ng++) {
                uint4 nb0, nb1;
                if (ng < 3) {
                    nb0 = ldg4(wfw + (ch*16 + 2*ng + 2)*128);
                    nb1 = ldg4(wfw + (ch*16 + 2*ng + 3)*128);
                } else if (ch < 7) {
                    nb0 = ldg4(wfw + ((ch+1)*16)*128);
                    nb1 = ldg4(wfw + ((ch+1)*16 + 1)*128);
                }
                mma_step(acc, ah, alo, b0, b1, 2*ng, 2*ng + 1);
                b0 = nb0; b1 = nb1;
            }
        }
    }

    // ---- layers 2..4: frag exchange via smem ----
    #pragma unroll 1
    for (int l = 1; l < 4; l++) {
        const float* bias = midbias[l-1];
        #pragma unroll
        for (int mt = 0; mt < 2; mt++) {
            #pragma unroll
            for (int ng = 0; ng < 4; ng++) {
                int ntE = 2*ng, ntO = 2*ng + 1;
                int cE = wn*64 + ntE*8 + 2*(lane & 3);
                float bE0 = bias[cE],     bE1 = bias[cE + 1];
                float bO0 = bias[cE + 8], bO1 = bias[cE + 9];
                float e0 = acc[mt][ntE][0] + bE0, e1 = acc[mt][ntE][1] + bE1;
                float e2 = acc[mt][ntE][2] + bE0, e3 = acc[mt][ntE][3] + bE1;
                float o0 = acc[mt][ntO][0] + bO0, o1 = acc[mt][ntO][1] + bO1;
                float o2 = acc[mt][ntO][2] + bO0, o3 = acc[mt][ntO][3] + bO1;
                e0 = e0 > 0.f ? e0 : 0.01f*e0;  e1 = e1 > 0.f ? e1 : 0.01f*e1;
                e2 = e2 > 0.f ? e2 : 0.01f*e2;  e3 = e3 > 0.f ? e3 : 0.01f*e3;
                o0 = o0 > 0.f ? o0 : 0.01f*o0;  o1 = o1 > 0.f ? o1 : 0.01f*o1;
                o2 = o2 > 0.f ? o2 : 0.01f*o2;  o3 = o3 > 0.f ? o3 : 0.01f*o3;
                uint32_t l0, l1, l2, l3;
                uint32_t h0 = bfpack2(e0, e1, l0);
                uint32_t h1 = bfpack2(e2, e3, l1);
                uint32_t h2 = bfpack2(o0, o1, l2);
                uint32_t h3 = bfpack2(o2, o3, l3);
                int base = ((wn*4 + ng)*8 + wm*2 + mt)*256 + lane*4;
                *reinterpret_cast<uint4*>(&sF[base])       = make_uint4(h0, h1, h2, h3);
                *reinterpret_cast<uint4*>(&sF[base + 128]) = make_uint4(l0, l1, l2, l3);
                #pragma unroll
                for (int q = 0; q < 4; q++) { acc[mt][ntE][q] = 0.f; acc[mt][ntO][q] = 0.f; }
            }
        }
        __syncthreads();
        const uint32_t* wfw = wfbase + woff[l] + wn*8*128 + lane*4;
        uint4 b0 = ldg4(wfw);
        uint4 b1 = ldg4(wfw + 128);
        #pragma unroll 1
        for (int ch = 0; ch < 8; ch++) {
            uint4 ah[2], alo[2];
            #pragma unroll
            for (int mt = 0; mt < 2; mt++) {
                int base = (ch*8 + wm*2 + mt)*256 + lane*4;
                ah[mt]  = *reinterpret_cast<const uint4*>(&sF[base]);
                alo[mt] = *reinterpret_cast<const uint4*>(&sF[base + 128]);
            }
            #pragma unroll
            for (int ng = 0; ng < 4; ng++) {
                uint4 nb0, nb1;
                if (ng < 3) {
                    nb0 = ldg4(wfw + (ch*16 + 2*ng + 2)*128);
                    nb1 = ldg4(wfw + (ch*16 + 2*ng + 3)*128);
                } else if (ch < 7) {
                    nb0 = ldg4(wfw + ((ch+1)*16)*128);
                    nb1 = ldg4(wfw + ((ch+1)*16 + 1)*128);
                }
                mma_step(acc, ah, alo, b0, b1, 2*ng, 2*ng + 1);
                b0 = nb0; b1 = nb1;
            }
        }
        __syncthreads();   // reads done before next conversion overwrites
    }

    // ---- final: lb4 + leaky, then fused classifier (x @ lw5 + lb5) ------
    float* sC = reinterpret_cast<float*>(sF);   // [ (wn*128 + rl)*8 + cls ]
    #pragma unroll
    for (int mt = 0; mt < 2; mt++) {
        #pragma unroll
        for (int half = 0; half < 2; half++) {
            float part[NCLS] = {0.f, 0.f, 0.f, 0.f, 0.f, 0.f};
            #pragma unroll
            for (int nt = 0; nt < 8; nt++) {
                #pragma unroll
                for (int j = 0; j < 2; j++) {
                    int c = wn*64 + nt*8 + 2*(lane & 3) + j;
                    float v = acc[mt][nt][half*2 + j] + lb4[c];
                    v = v > 0.f ? v : 0.01f*v;
                    #pragma unroll
                    for (int cls = 0; cls < NCLS; cls++)
                        part[cls] += v * __ldg(&lw5[c*NCLS + cls]);
                }
            }
            #pragma unroll
            for (int cls = 0; cls < NCLS; cls++) {
                part[cls] += __shfl_xor_sync(0xffffffffu, part[cls], 1);
                part[cls] += __shfl_xor_sync(0xffffffffu, part[cls], 2);
            }
            if ((lane & 3) == 0) {
                int rl = wm*32 + mt*16 + (lane >> 2) + half*8;
                #pragma unroll
                for (int cls = 0; cls < NCLS; cls++)
                    sC[(wn*128 + rl)*8 + cls] = part[cls];
            }
        }
    }
    __syncthreads();
    for (int idx = tid; idx < 128*NCLS; idx += 256) {
        int rl = idx / NCLS, cls = idx % NCLS;
        int r = m0 + rl;
        if (r < M)
            out[(size_t)r*NCLS + cls] =
                sC[rl*8 + cls] + sC[(128 + rl)*8 + cls] + lb5[cls];
    }
}

// ---- fused softmax + aggregation, block (96 thr) per node ---------------
__global__ __launch_bounds__(96)
void agg_kernel(const float* __restrict__ bias, uint32_t* __restrict__ fragOut)
{
    __shared__ int    sSrc[CAP];
    __shared__ float  sE[3][CAP];
    __shared__ float4 sh4[3][32];
    int n = blockIdx.x;
    int t = threadIdx.x, head = t >> 5, lane = t & 31;
    int beg = g_rowptr[n], end = g_rowptr[n+1];
    int deg = end - beg;
    int cached = deg < CAP ? deg : CAP;
    for (int j = t; j < cached; j += 96) sSrc[j] = g_srcs[beg + j];
    __syncthreads();

    float er_n = g_er[n*HH + head];
    float mx = -1e30f;
    for (int j = lane; j < deg; j += 32) {
        int s = (j < CAP) ? sSrc[j] : g_srcs[beg + j];
        float v = g_el[s*HH + head] + er_n;
        v = v > 0.f ? v : 0.2f*v;
        if (j < CAP) sE[head][j] = v;
        mx = fmaxf(mx, v);
    }
    #pragma unroll
    for (int o = 16; o; o >>= 1) mx = fmaxf(mx, __shfl_xor_sync(0xffffffffu, mx, o));
    float sum = 0.f;
    for (int j = lane; j < deg; j += 32) {
        float v;
        if (j < CAP) v = sE[head][j];
        else {
            int s = g_srcs[beg + j];
            v = g_el[s*HH + head] + er_n;
            v = v > 0.f ? v : 0.2f*v;
        }
        float e = expf(v - mx);
        if (j < CAP) sE[head][j] = e;
        sum += e;
    }
    #pragma unroll
    for (int o = 16; o; o >>= 1) sum += __shfl_xor_sync(0xffffffffu, sum, o);
    float inv = 1.f / (sum + 1e-9f);
    __syncwarp();

    // weighted gather, unroll 4 (MLP_eff ~4)
    const __half* hb = &g_h[head*HIDN + lane*4];
    float4 a = make_float4(0.f, 0.f, 0.f, 0.f);
    int jn = 0;
    for (; jn + 3 < cached; jn += 4) {
        int   s0 = sSrc[jn],   s1 = sSrc[jn+1], s2 = sSrc[jn+2], s3 = sSrc[jn+3];
        float w0 = sE[head][jn],   w1 = sE[head][jn+1];
        float w2 = sE[head][jn+2], w3 = sE[head][jn+3];
        uint2 u0 = *(const uint2*)&hb[(size_t)s0*HF];
        uint2 u1 = *(const uint2*)&hb[(size_t)s1*HF];
        uint2 u2 = *(const uint2*)&hb[(size_t)s2*HF];
        uint2 u3 = *(const uint2*)&hb[(size_t)s3*HF];
        float2 p00 = __half22float2(*reinterpret_cast<__half2*>(&u0.x));
        float2 p01 = __half22float2(*reinterpret_cast<__half2*>(&u0.y));
        float2 p10 = __half22float2(*reinterpret_cast<__half2*>(&u1.x));
        float2 p11 = __half22float2(*reinterpret_cast<__half2*>(&u1.y));
        float2 p20 = __half22float2(*reinterpret_cast<__half2*>(&u2.x));
        float2 p21 = __half22float2(*reinterpret_cast<__half2*>(&u2.y));
        float2 p30 = __half22float2(*reinterpret_cast<__half2*>(&u3.x));
        float2 p31 = __half22float2(*reinterpret_cast<__half2*>(&u3.y));
        a.x += w0*p00.x + w1*p10.x + w2*p20.x + w3*p30.x;
        a.y += w0*p00.y + w1*p10.y + w2*p20.y + w3*p30.y;
        a.z += w0*p01.x + w1*p11.x + w2*p21.x + w3*p31.x;
        a.w += w0*p01.y + w1*p11.y + w2*p21.y + w3*p31.y;
    }
    for (; jn < cached; jn++) {
        int s = sSrc[jn];
        float w = sE[head][jn];
        uint2 u = *(const uint2*)&hb[(size_t)s*HF];
        float2 p0 = __half22float2(*reinterpret_cast<__half2*>(&u.x));
        float2 p1 = __half22float2(*reinterpret_cast<__half2*>(&u.y));
        a.x += w*p0.x; a.y += w*p0.y; a.z += w*p1.x; a.w += w*p1.y;
    }
    for (int j = beg + CAP; j < end; j++) {      // rare fallback
        int s = g_srcs[j];
        float v = g_el[s*HH + head] + er_n;
        v = v > 0.f ? v : 0.2f*v;
        float w = expf(v - mx);
        uint2 u = *(const uint2*)&hb[(size_t)s*HF];
        float2 p0 = __half22float2(*reinterpret_cast<__half2*>(&u.x));
        float2 p1 = __half22float2(*reinterpret_cast<__half2*>(&u.y));
        a.x += w*p0.x; a.y += w*p0.y; a.z += w*p1.x; a.w += w*p1.y;
    }

    const float4 b4 = *(const float4*)&bias[head*HIDN + lane*4];
    a.x = a.x*inv + b4.x;  a.y = a.y*inv + b4.y;
    a.z = a.z*inv + b4.z;  a.w = a.w*inv + b4.w;
    a.x = a.x > 0.f ? a.x : 0.01f*a.x;
    a.y = a.y > 0.f ? a.y : 0.01f*a.y;
    a.z = a.z > 0.f ? a.z : 0.01f*a.z;
    a.w = a.w > 0.f ? a.w : 0.01f*a.w;
    sh4[head][lane] = a;
    __syncthreads();
    if (t < 32) {
        float4 r0 = sh4[0][t], r1 = sh4[1][t], r2 = sh4[2][t];
        float o[4];
        o[0] = (r0.x + r1.x + r2.x) * (1.f/3.f);
        o[1] = (r0.y + r1.y + r2.y) * (1.f/3.f);
        o[2] = (r0.z + r1.z + r2.z) * (1.f/3.f);
        o[3] = (r0.w + r1.w + r2.w) * (1.f/3.f);
        uint32_t lo01, lo23;
        uint32_t hi01 = bfpack2(o[0], o[1], lo01);
        uint32_t hi23 = bfpack2(o[2], o[3], lo23);
        int a0 = frag_addr(n, t*4);
        int a2 = frag_addr(n, t*4 + 2);
        fragOut[a0]       = hi01;
        fragOut[a0 + 128] = lo01;
        fragOut[a2]       = hi23;
        fragOut[a2 + 128] = lo23;
    }
}

// -------------------------------------------------------------------------
extern "C" void kernel_launch(void* const* d_in, const int* in_sizes, int n_in,
                              void* d_out, int out_size)
{
    const float* in_feat = (const float*)d_in[0];
    const int*   src     = (const int*)  d_in[1];
    const int*   dst     = (const int*)  d_in[2];
    const float* W1  = (const float*)d_in[3];
    const float* al1 = (const float*)d_in[4];
    const float* ar1 = (const float*)d_in[5];
    const float* b1  = (const float*)d_in[6];
    const float* W2  = (const float*)d_in[7];
    const float* al2 = (const float*)d_in[8];
    const float* ar2 = (const float*)d_in[9];
    const float* b2  = (const float*)d_in[10];
    const float* lw1 = (const float*)d_in[11];
    const float* lb1 = (const float*)d_in[12];
    const float* lw2 = (const float*)d_in[13];
    const float* lb2 = (const float*)d_in[14];
    const float* lw3 = (const float*)d_in[15];
    const float* lb3 = (const float*)d_in[16];
    const float* lw4 = (const float*)d_in[17];
    const float* lb4 = (const float*)d_in[18];
    const float* lw5 = (const float*)d_in[19];
    const float* lb5 = (const float*)d_in[20];
    float* out = (float*)d_out;

    uint32_t *pwf, *pfA;
    cudaGetSymbolAddress((void**)&pwf, g_wf);
    cudaGetSymbolAddress((void**)&pfA, g_afragA);

    cudaFuncSetAttribute(mlp_kernel, cudaFuncAttributeMaxDynamicSharedMemorySize, 65536);

    const int TB = 256;
    dim3 g_gat(HF/128, MBLKS);     // (3, 391)

    // Round-13-proven footprint: ONE side stream + TWO events, fresh per
    // call (no caching, no device allocation).
    cudaStream_t s2;
    cudaStreamCreateWithFlags(&s2, cudaStreamNonBlocking);
    cudaEvent_t eFork, eCSR;
    cudaEventCreateWithFlags(&eFork, cudaEventDisableTiming);
    cudaEventCreateWithFlags(&eCSR,  cudaEventDisableTiming);

    // fork
    cudaEventRecord(eFork, 0);
    cudaStreamWaitEvent(s2, eFork, 0);

    // ---- branch B (s2): CSR build ----
    zero_deg_kernel<<<(NN + TB - 1)/TB, TB, 0, s2>>>();
    hist_kernel<<<(EE + TB - 1)/TB, TB, 0, s2>>>(dst);
    scan_kernel<<<1, 1024, 0, s2>>>();
    scatter_kernel<<<(EE + TB - 1)/TB, TB, 0, s2>>>(src, dst);
    cudaEventRecord(eCSR, s2);

    // ---- branch A (main): pre-splits, then GAT layer 1 GEMM ----
    presplit_w_kernel<<<(81920 + TB - 1)/TB, TB>>>(W1, W2, lw1, lw2, lw3, lw4);
    presplit_a_kernel<<<(MBLKS*128*64 + TB - 1)/TB, TB>>>(in_feat);
    gatgemm_kernel<<<g_gat, 256>>>(pfA, pwf + WF_W1, NN, al1, ar1);

    // join CSR before agg1
    cudaStreamWaitEvent(0, eCSR, 0);

    // ---- GAT layer 1 edge phase ----
    agg_kernel<<<NN, 96>>>(b1, pfA);

    // ---- GAT layer 2 ----
    gatgemm_kernel<<<g_gat, 256>>>(pfA, pwf + WF_W2, NN, al2, ar2);
    agg_kernel<<<NN, 96>>>(b2, pfA);

    // ---- fused MLP (lin1..lin4 + classifier) ----
    mlp_kernel<<<MBLKS, 256, 65536>>>(pfA, pwf, lb1, lb2, lb3, lb4, lw5, lb5, out, NN);
}